// round 11
// baseline (speedup 1.0000x reference)
#include <cuda_runtime.h>
#include <cuda_fp16.h>
#include <math.h>

// SwapV2: Gaussian soft-gather, 3.75-sigma truncated. B=8, C=32, H=W=64 fp32.
// R10: R8 structure (LDS.128 8-tap chunks, ROWH=72) +
//  (a) 4-way split fp32 accumulators (break FFMA2 dependency chains),
//  (b) software-pipelined pixel setup (prefetch next pixel's queue slot and
//      ex/ey/sigma scalars so the LDG latency hides under the current loop).

#define HH 64
#define WW 64
#define HWP 4096
#define CCN 32
#define SLAB_ROWS 48
#define ROWH 72
#define CROW (CCN * ROWH)
#define NWARPS 32
#define PTILES 9
#define KTRUNC 3.75f
#define LIST_N 464

#define SIN_HALVES (SLAB_ROWS * CCN * ROWH)
#define SIN_BYTES  (SIN_HALVES * 2)                 // 221184
#define SW_BYTES   (NWARPS * 256)                   // wy[32]f32 + wx[48]h per warp
#define SMEM_BYTES (SIN_BYTES + SW_BYTES + LIST_N * 4 + 8)

typedef unsigned long long ull;

#define FMA2(d, a, b, c) asm("fma.rn.f32x2 %0, %1, %2, %3;" : "=l"(d) : "l"(a), "l"(b), "l"(c))
#define PACK2(d, lo, hi) asm("mov.b64 %0, {%1, %2};" : "=l"(d) : "f"(lo), "f"(hi))
#define UNPACK2(lo, hi, s) asm("mov.b64 {%0, %1}, %2;" : "=f"(lo), "=f"(hi) : "l"(s))

#define H2(x) (*(const __half2*)&(x))

// per 8-tap chunk: 4-deep fp16 chain -> f32 pair -> FFMA2 into dst
#define CHUNK(dst, wq, d, wy2) {                                    \
    __half2 _h = __hmul2(H2((wq).x), H2((d).x));                    \
    _h = __hfma2(H2((wq).y), H2((d).y), _h);                        \
    _h = __hfma2(H2((wq).z), H2((d).z), _h);                        \
    _h = __hfma2(H2((wq).w), H2((d).w), _h);                        \
    float2 _f = __half22float2(_h);                                 \
    ull _q; PACK2(_q, _f.x, _f.y);                                  \
    FMA2(dst, wy2, _q, dst); }

// 2-row unrolled body; chunk j alternates accumulators by parity
#define BODY2(MCH) {                                                \
    uint4 wxq[MCH];                                                 \
    _Pragma("unroll")                                               \
    for (int j = 0; j < MCH; j++)                                   \
        wxq[j] = *(const uint4*)(s_wxh + 8 * j);                    \
    for (int t = 0; t < wu; t += 2) {                               \
        float2 wyf = *(const float2*)(s_wy + t);                    \
        ull wyA; PACK2(wyA, wyf.x, wyf.x);                          \
        ull wyB; PACK2(wyB, wyf.y, wyf.y);                          \
        const __half* pa = prow;                                    \
        const __half* pb = (t + 1 < wu) ? prow + CROW : prow;       \
        _Pragma("unroll")                                           \
        for (int j = 0; j < MCH; j++) {                             \
            uint4 dA = *(const uint4*)(pa + 8 * j);                 \
            uint4 dB = *(const uint4*)(pb + 8 * j);                 \
            if (j & 1) { CHUNK(accA1, wxq[j], dA, wyA);             \
                         CHUNK(accB1, wxq[j], dB, wyB); }           \
            else       { CHUNK(accA0, wxq[j], dA, wyA);             \
                         CHUNK(accB0, wxq[j], dB, wyB); }           \
        }                                                           \
        prow += 2 * CROW;                                           \
    } }

// 4-row unrolled body for narrow windows; rows spread over all 4 accs
#define BODY4(MCH) {                                                \
    uint4 wxq[MCH];                                                 \
    _Pragma("unroll")                                               \
    for (int j = 0; j < MCH; j++)                                   \
        wxq[j] = *(const uint4*)(s_wxh + 8 * j);                    \
    for (int t = 0; t < wu; t += 4) {                               \
        float4 wyf = *(const float4*)(s_wy + t);                    \
        ull wyA; PACK2(wyA, wyf.x, wyf.x);                          \
        ull wyB; PACK2(wyB, wyf.y, wyf.y);                          \
        ull wyC; PACK2(wyC, wyf.z, wyf.z);                          \
        ull wyD; PACK2(wyD, wyf.w, wyf.w);                          \
        const __half* pa = prow;                                    \
        const __half* pb = (t + 1 < wu) ? prow + CROW : prow;       \
        const __half* pc = (t + 2 < wu) ? prow + 2 * CROW : prow;   \
        const __half* pd = (t + 3 < wu) ? prow + 3 * CROW : prow;   \
        _Pragma("unroll")                                           \
        for (int j = 0; j < MCH; j++) {                             \
            uint4 dA = *(const uint4*)(pa + 8 * j);                 \
            uint4 dB = *(const uint4*)(pb + 8 * j);                 \
            uint4 dC = *(const uint4*)(pc + 8 * j);                 \
            uint4 dD = *(const uint4*)(pd + 8 * j);                 \
            CHUNK(accA0, wxq[j], dA, wyA);                          \
            CHUNK(accB0, wxq[j], dB, wyB);                          \
            CHUNK(accA1, wxq[j], dC, wyC);                          \
            CHUNK(accB1, wxq[j], dD, wyD);                          \
        }                                                           \
        prow += 4 * CROW;                                           \
    } }

__global__ __launch_bounds__(1024, 1)
void swapv2_kernel(const float* __restrict__ inp,
                   const float* __restrict__ exPx,
                   const float* __restrict__ exPy,
                   const float* __restrict__ sigx,
                   const float* __restrict__ sigy,
                   float* __restrict__ out)
{
    extern __shared__ char smem[];
    __half* s_in  = (__half*)smem;                          // [48][32][ROWH]
    char*   s_wb  = smem + SIN_BYTES;                       // per-warp 256B
    int*    s_list = (int*)(smem + SIN_BYTES + SW_BYTES);
    int*    s_cnt  = s_list + LIST_N;

    const int tid  = threadIdx.x;
    const int w    = tid >> 5;
    const int lane = tid & 31;
    const int tile = blockIdx.x;                            // 0..8
    const int slab = blockIdx.y;                            // 0..1
    const int b    = blockIdx.z;                            // 0..7
    const int ubase = slab * 16;

    if (tid < 2) s_cnt[tid] = 0;
    __syncthreads();

    const int pbeg = (HWP * tile) / PTILES;
    const int pend = (HWP * (tile + 1)) / PTILES;

    // ---- build pixel list (slab membership) ----
    for (int p = pbeg + tid; p < pend; p += 1024) {
        int idx = b * HWP + p;
        float ey = exPy[idx], sy = sigy[idx];
        int u0 = max(0,      (int)ceilf (ey - KTRUNC * sy));
        int u1 = min(HH - 1, (int)floorf(ey + KTRUNC * sy));
        int ms = (u1 <= 47 && (u0 < 16 || ey < 31.5f)) ? 0 : 1;
        if (ms == slab) s_list[atomicAdd(&s_cnt[0], 1)] = p;
    }

    // ---- stage 48-row fp16 slab, pads zeroed ----
    {
        const float* gsrc = inp + (size_t)b * CCN * HWP;
        for (int j = tid; j < SLAB_ROWS * CCN * 9; j += 1024) {
            int q = j % 9;
            int r = j / 9;
            uint4 st = make_uint4(0u, 0u, 0u, 0u);
            if (q < 8) {
                int u = r >> 5, c = r & 31;
                const float* g = gsrc + (size_t)c * HWP + (ubase + u) * WW + 8 * q;
                float4 a = *(const float4*)g;
                float4 bb = *(const float4*)(g + 4);
                __half2 h0 = __float22half2_rn(make_float2(a.x, a.y));
                __half2 h1 = __float22half2_rn(make_float2(a.z, a.w));
                __half2 h2 = __float22half2_rn(make_float2(bb.x, bb.y));
                __half2 h3 = __float22half2_rn(make_float2(bb.z, bb.w));
                st.x = *(unsigned*)&h0; st.y = *(unsigned*)&h1;
                st.z = *(unsigned*)&h2; st.w = *(unsigned*)&h3;
            }
            *(uint4*)(s_in + r * ROWH + 8 * q) = st;
        }
    }
    __syncthreads();

    const int cnt = s_cnt[0];
    float*  s_wy  = (float*)(s_wb + w * 256);               // 32 f32
    __half* s_wxh = (__half*)(s_wb + w * 256 + 128);        // 48 halves

    // ---- software-pipelined work queue ----
    int k = 0;
    if (lane == 0) k = atomicAdd(&s_cnt[1], 1);
    k = __shfl_sync(0xFFFFFFFFu, k, 0);
    bool valid = k < cnt;
    int p = 0; float ey = 0.f, ex = 0.f, sy = 1.f, sx = 1.f;
    if (valid) {
        p = s_list[k];
        int idx = b * HWP + p;
        ey = exPy[idx]; ex = exPx[idx]; sy = sigy[idx]; sx = sigx[idx];
    }

    while (valid) {
        // --- prefetch next pixel's slot + scalars (hides atomic+LDS+LDG) ---
        int k2 = 0;
        if (lane == 0) k2 = atomicAdd(&s_cnt[1], 1);
        k2 = __shfl_sync(0xFFFFFFFFu, k2, 0);
        bool valid2 = k2 < cnt;
        int p2 = 0; float ey2 = 0.f, ex2 = 0.f, sy2 = 1.f, sx2 = 1.f;
        if (valid2) {
            p2 = s_list[k2];
            int idx2 = b * HWP + p2;
            ey2 = exPy[idx2]; ex2 = exPx[idx2];
            sy2 = sigy[idx2]; sx2 = sigx[idx2];
        }

        // --- process current pixel ---
        int u0 = max(0,      (int)ceilf (ey - KTRUNC * sy));
        int u1 = min(HH - 1, (int)floorf(ey + KTRUNC * sy));
        int v0 = max(0,      (int)ceilf (ex - KTRUNC * sx));
        int v1 = min(WW - 1, (int)floorf(ex + KTRUNC * sx));
        int v0a = v0 & ~7;

        float invsy = 1.0f / sy, invsx = 1.0f / sx;
        int uu = u0 + lane;
        float dy = ((float)uu - ey) * invsy;
        float wy = (uu <= u1) ? __expf(-0.5f * dy * dy) : 0.0f;
        int vv = v0 + lane;
        float dx = ((float)vv - ex) * invsx;
        float wxf = (vv <= v1) ? __expf(-0.5f * dx * dx) : 0.0f;
        __half wxh = __float2half_rn(wxf);
        float wxr = __half2float(wxh);       // Z must match fp16 weights

        float sumy = wy, sumx = wxr;
        #pragma unroll
        for (int o = 16; o; o >>= 1) {
            sumy += __shfl_xor_sync(0xFFFFFFFFu, sumy, o);
            sumx += __shfl_xor_sync(0xFFFFFFFFu, sumx, o);
        }
        float invZ = 1.0f / (sumy * sumx + 1e-8f);

        s_wy[lane] = wy;
        if (lane < 24) ((unsigned*)s_wxh)[lane] = 0u;
        __syncwarp();
        if (lane <= v1 - v0) s_wxh[(v0 - v0a) + lane] = wxh;
        __syncwarp();

        const int wu  = u1 - u0 + 1;                 // <= 23
        const int mch = ((v1 - v0a) >> 3) + 1;       // <= 4

        const __half* prow = s_in + ((u0 - ubase) * CCN + lane) * ROWH + v0a;
        ull accA0 = 0ULL, accA1 = 0ULL, accB0 = 0ULL, accB1 = 0ULL;

        switch (mch) {
            case 1: BODY4(1); break;
            case 2: BODY4(2); break;
            case 3: BODY2(3); break;
            case 4: BODY2(4); break;
            default: BODY2(5); break;
        }

        float a0, a1, b0, b1, c0, c1, d0, d1;
        UNPACK2(a0, a1, accA0);
        UNPACK2(b0, b1, accA1);
        UNPACK2(c0, c1, accB0);
        UNPACK2(d0, d1, accB1);
        out[(size_t)(b * CCN + lane) * HWP + p] =
            ((a0 + a1) + (b0 + b1) + ((c0 + c1) + (d0 + d1))) * invZ;
        __syncwarp();

        // --- rotate pipeline ---
        k = k2; p = p2; valid = valid2;
        ey = ey2; ex = ex2; sy = sy2; sx = sx2;
    }
}

extern "C" void kernel_launch(void* const* d_in, const int* in_sizes, int n_in,
                              void* d_out, int out_size) {
    (void)in_sizes; (void)n_in; (void)out_size;
    const float* inp  = (const float*)d_in[0];
    const float* exPx = (const float*)d_in[1];
    const float* exPy = (const float*)d_in[2];
    const float* sigx = (const float*)d_in[3];
    const float* sigy = (const float*)d_in[4];
    float* out = (float*)d_out;

    cudaFuncSetAttribute(swapv2_kernel,
                         cudaFuncAttributeMaxDynamicSharedMemorySize, SMEM_BYTES);
    dim3 grid(PTILES, 2, 8);          // 144 blocks = one full wave
    swapv2_kernel<<<grid, 1024, SMEM_BYTES>>>(inp, exPx, exPy, sigx, sigy, out);
}

// round 14
// speedup vs baseline: 1.2740x; 1.2740x over previous
#include <cuda_runtime.h>
#include <cuda_fp16.h>
#include <cstdint>
#include <math.h>

// SwapV2 dense via mma.sync.m16n8k16 (fp16 in, f32 acc). B=8, C=32, H=W=64.
// Stage 1 (prepass): input fp32 -> fp16 scratch, layout [b][uchunk8][n=u4..*32+c][v64].
// Stage 2 (main): per CTA (128 px, 1 batch): S[p, u8*32+c] = Wx[p,v] @ In[n,v]^T
//   via mma.sync; epilogue acc[p,c] += wy[p,u] * S from register fragments.
// Warp = (64-px strip) x (8-channel block): 8 warps, A frags resident in regs.

#define HWP 4096
#define SW(o) ((o) ^ (((o) >> 3) & 0x70))

#define SM_A   0                    // 128 rows x 128B (wx fp16, swizzled)
#define SM_B   16384                // 2 x 256 rows x 128B
#define SM_WY  (16384 + 65536)      // [64 u][128 px] f32
#define SM_SX  (SM_WY + 32768)      // 128 f32
#define SM_SY  (SM_SX + 512)        // 128 f32
#define SM_TOT (SM_SY + 512)        // 115712 B

__device__ __half g_fp16[8 * 8 * 256 * 64];   // 2MB fp16 scratch

__device__ __forceinline__ uint32_t s32(const void* p) {
    uint32_t a;
    asm("{ .reg .u64 t; cvta.to.shared.u64 t, %1; cvt.u32.u64 %0, t; }" : "=r"(a) : "l"(p));
    return a;
}

#define CPA16(dst, src) \
    asm volatile("cp.async.ca.shared.global [%0], [%1], 16;" :: "r"(dst), "l"(src) : "memory")
#define CPA_COMMIT() asm volatile("cp.async.commit_group;" ::: "memory")
#define CPA_WAIT0()  asm volatile("cp.async.wait_group 0;" ::: "memory")

#define LDM4(r0, r1, r2, r3, a) \
    asm volatile("ldmatrix.sync.aligned.m8n8.x4.shared.b16 {%0,%1,%2,%3}, [%4];" \
        : "=r"(r0), "=r"(r1), "=r"(r2), "=r"(r3) : "r"(a))

#define MMA16816(d, a0, a1, a2, a3, b0, b1) \
    asm volatile("mma.sync.aligned.m16n8k16.row.col.f32.f16.f16.f32 " \
        "{%0,%1,%2,%3},{%4,%5,%6,%7},{%8,%9},{%0,%1,%2,%3};" \
        : "+f"((d)[0]), "+f"((d)[1]), "+f"((d)[2]), "+f"((d)[3]) \
        : "r"(a0), "r"(a1), "r"(a2), "r"(a3), "r"(b0), "r"(b1))

// ---------------- prepass: fp32 image -> fp16 scratch ----------------
__global__ void prep_kernel(const float* __restrict__ inp) {
    int g = blockIdx.x * 256 + threadIdx.x;      // 0..131071 (16B units)
    int q  = g & 7;                               // 16B unit within 128B row
    int n  = (g >> 3) & 255;                      // row = u_local*32 + c
    int ch = (g >> 11) & 7;                       // u-chunk
    int b  = g >> 14;
    int c  = n & 31;
    int u  = ch * 8 + (n >> 5);
    const float* s = inp + ((size_t)(b * 32 + c) * HWP + u * 64 + q * 8);
    float4 f0 = *(const float4*)s;
    float4 f1 = *(const float4*)(s + 4);
    __half2 h0 = __float22half2_rn(make_float2(f0.x, f0.y));
    __half2 h1 = __float22half2_rn(make_float2(f0.z, f0.w));
    __half2 h2 = __float22half2_rn(make_float2(f1.x, f1.y));
    __half2 h3 = __float22half2_rn(make_float2(f1.z, f1.w));
    uint4 st;
    st.x = *(uint32_t*)&h0; st.y = *(uint32_t*)&h1;
    st.z = *(uint32_t*)&h2; st.w = *(uint32_t*)&h3;
    *(uint4*)(g_fp16 + (((size_t)(b * 8 + ch) * 256 + n) * 64 + q * 8)) = st;
}

// ---------------- main kernel ----------------
__global__ __launch_bounds__(256, 1)
void swapv2_mma(const float* __restrict__ exPx, const float* __restrict__ exPy,
                const float* __restrict__ sigx, const float* __restrict__ sigy,
                float* __restrict__ out)
{
    extern __shared__ char smem[];
    const uint32_t sb = s32(smem);
    const int tid  = threadIdx.x;
    const int lane = tid & 31;
    const int wid  = tid >> 5;
    const int s    = wid >> 2;                  // px strip (0/1): 64 px
    const int cb   = wid & 3;                   // channel block: 8 c
    const int tile = blockIdx.x;                // 0..31 (128 px each)
    const int b    = blockIdx.y;

    // ---- stage chunk 0 (cp.async; prepass output) ----
    {
        const __half* src = g_fp16 + (size_t)(b * 8 + 0) * 16384;
        #pragma unroll
        for (int j = 0; j < 8; j++) {
            int idx = tid + j * 256;
            int q = idx & 7, n = idx >> 3;
            uint32_t dst = sb + SM_B + SW((uint32_t)n * 128 + q * 16);
            CPA16(dst, src + n * 64 + q * 8);
        }
        CPA_COMMIT();
    }

    // ---- build wx (A matrix, fp16 swz) / wy (f32) / row sums ----
    if (tid < 128) {
        int px = tid;
        int pidx = b * HWP + tile * 128 + px;
        float ex = exPx[pidx];
        float iv = 0.5f / (sigx[pidx] * sigx[pidx]);
        float sumx = 0.f;
        #pragma unroll
        for (int j = 0; j < 8; j++) {
            uint32_t hh[4];
            #pragma unroll
            for (int h = 0; h < 4; h++) {
                float d0 = (float)(j * 8 + h * 2) - ex;
                float d1 = d0 + 1.f;
                __half2 h2 = __float22half2_rn(make_float2(__expf(-d0 * d0 * iv),
                                                           __expf(-d1 * d1 * iv)));
                float2 bk = __half22float2(h2);
                sumx += bk.x + bk.y;
                hh[h] = *(uint32_t*)&h2;
            }
            *(uint4*)(smem + SM_A + SW((uint32_t)px * 128 + j * 16)) =
                make_uint4(hh[0], hh[1], hh[2], hh[3]);
        }
        ((float*)(smem + SM_SX))[px] = sumx;
    } else {
        int px = tid - 128;
        int pidx = b * HWP + tile * 128 + px;
        float ey = exPy[pidx];
        float iv = 0.5f / (sigy[pidx] * sigy[pidx]);
        float sumy = 0.f;
        float* wyp = (float*)(smem + SM_WY);
        #pragma unroll 8
        for (int u = 0; u < 64; u++) {
            float d = (float)u - ey;
            float w = __expf(-d * d * iv);
            wyp[u * 128 + px] = w;
            sumy += w;
        }
        ((float*)(smem + SM_SY))[px] = sumy;
    }
    __syncthreads();

    // ---- load A fragments (resident): 4 m-tiles x 4 k-steps x 4 regs ----
    uint32_t A[4][4][4];
    {
        int r8 = lane & 7, hi8 = (lane >> 3) & 1, kb = lane >> 4;
        #pragma unroll
        for (int mt = 0; mt < 4; mt++)
            #pragma unroll
            for (int ks = 0; ks < 4; ks++) {
                uint32_t off = (uint32_t)(s * 64 + mt * 16 + r8 + hi8 * 8) * 128
                             + ks * 32 + kb * 16;
                LDM4(A[mt][ks][0], A[mt][ks][1], A[mt][ks][2], A[mt][ks][3],
                     sb + SM_A + SW(off));
            }
    }

    float acc[16];
    #pragma unroll
    for (int i = 0; i < 16; i++) acc[i] = 0.f;

    // ---- chunk loop: wait k, stage k+1, compute k ----
    for (int k = 0; k < 8; k++) {
        CPA_WAIT0();
        __syncthreads();
        if (k < 7) {
            const __half* src = g_fp16 + (size_t)(b * 8 + k + 1) * 16384;
            uint32_t bufo = SM_B + ((k + 1) & 1) * 32768;
            #pragma unroll
            for (int j = 0; j < 8; j++) {
                int idx = tid + j * 256;
                int q = idx & 7, n = idx >> 3;
                CPA16(sb + bufo + SW((uint32_t)n * 128 + q * 16), src + n * 64 + q * 8);
            }
            CPA_COMMIT();
        }

        const uint32_t sbB = sb + SM_B + (k & 1) * 32768;
        const float* wyp = (const float*)(smem + SM_WY);
        #pragma unroll 1
        for (int uu = 0; uu < 8; uu++) {
            int nb = uu * 32 + cb * 8 + (lane & 7);
            uint32_t offb = (uint32_t)nb * 128 + (lane >> 3) * 16;
            uint32_t bb[8];
            LDM4(bb[0], bb[1], bb[2], bb[3], sbB + SW(offb));
            LDM4(bb[4], bb[5], bb[6], bb[7], sbB + SW(offb + 64));

            float S[16];
            #pragma unroll
            for (int i = 0; i < 16; i++) S[i] = 0.f;
            #pragma unroll
            for (int ks = 0; ks < 4; ks++)
                #pragma unroll
                for (int mt = 0; mt < 4; mt++)
                    MMA16816(&S[mt * 4], A[mt][ks][0], A[mt][ks][1],
                             A[mt][ks][2], A[mt][ks][3], bb[2 * ks], bb[2 * ks + 1]);

            const float* wyrow = wyp + (k * 8 + uu) * 128;
            int g4 = lane >> 2;
            #pragma unroll
            for (int mt = 0; mt < 4; mt++) {
                int px0 = s * 64 + mt * 16 + g4;
                float wy0 = wyrow[px0];
                float wy1 = wyrow[px0 + 8];
                acc[mt * 4 + 0] = fmaf(wy0, S[mt * 4 + 0], acc[mt * 4 + 0]);
                acc[mt * 4 + 1] = fmaf(wy0, S[mt * 4 + 1], acc[mt * 4 + 1]);
                acc[mt * 4 + 2] = fmaf(wy1, S[mt * 4 + 2], acc[mt * 4 + 2]);
                acc[mt * 4 + 3] = fmaf(wy1, S[mt * 4 + 3], acc[mt * 4 + 3]);
            }
        }
    }

    // ---- write out: out[b, c, pg] = acc * invZ ----
    const float* sx = (const float*)(smem + SM_SX);
    const float* sy = (const float*)(smem + SM_SY);
    int g4 = lane >> 2, t4 = lane & 3;
    int c0 = cb * 8 + t4 * 2;
    #pragma unroll
    for (int mt = 0; mt < 4; mt++) {
        int px0 = s * 64 + mt * 16 + g4;
        int px1 = px0 + 8;
        float iz0 = 1.0f / (sx[px0] * sy[px0] + 1e-8f);
        float iz1 = 1.0f / (sx[px1] * sy[px1] + 1e-8f);
        size_t base = (size_t)(b * 32 + c0) * HWP + tile * 128;
        out[base + px0]       = acc[mt * 4 + 0] * iz0;
        out[base + HWP + px0] = acc[mt * 4 + 1] * iz0;
        out[base + px1]       = acc[mt * 4 + 2] * iz1;
        out[base + HWP + px1] = acc[mt * 4 + 3] * iz1;
    }
}

extern "C" void kernel_launch(void* const* d_in, const int* in_sizes, int n_in,
                              void* d_out, int out_size) {
    (void)in_sizes; (void)n_in; (void)out_size;
    const float* inp  = (const float*)d_in[0];
    const float* exPx = (const float*)d_in[1];
    const float* exPy = (const float*)d_in[2];
    const float* sigx = (const float*)d_in[3];
    const float* sigy = (const float*)d_in[4];
    float* out = (float*)d_out;

    prep_kernel<<<512, 256>>>(inp);
    cudaFuncSetAttribute(swapv2_mma,
                         cudaFuncAttributeMaxDynamicSharedMemorySize, SM_TOT);
    dim3 grid(32, 8);                 // 256 CTAs
    swapv2_mma<<<grid, 256, SM_TOT>>>(exPx, exPy, sigx, sigy, out);
}

// round 15
// speedup vs baseline: 1.4321x; 1.1242x over previous
#include <cuda_runtime.h>
#include <cuda_fp16.h>
#include <cstdint>
#include <math.h>

// SwapV2 dense via mma.sync.m16n8k16 (fp16 in, f32 acc). B=8, C=32, H=W=64.
// R15: 512 thr/CTA, 256 px/CTA, grid 16x8 = 128 CTAs = one wave.
// Warp = (32-px strip: 2 m16 tiles) x (16-ch block: 2 n8 blocks). 16 warps
// -> 4 warps/SMSP. wy stored fp16 (Z from rounded halves).

#define HWP 4096
#define SW(o) ((o) ^ (((o) >> 3) & 0x70))

#define SM_A   0                          // 256 rows x 128B (wx fp16 swz)
#define SM_B   32768                      // 2 x 256 rows x 128B
#define SM_WY  (32768 + 65536)            // [64 u][256 px] fp16 = 32KB
#define SM_SX  (SM_WY + 32768)            // 256 f32
#define SM_SY  (SM_SX + 1024)             // 256 f32
#define SM_TOT (SM_SY + 1024)             // 133120 B

__device__ __half g_fp16[8 * 8 * 256 * 64];   // 2MB fp16 scratch

__device__ __forceinline__ uint32_t s32(const void* p) {
    uint32_t a;
    asm("{ .reg .u64 t; cvta.to.shared.u64 t, %1; cvt.u32.u64 %0, t; }" : "=r"(a) : "l"(p));
    return a;
}

#define CPA16(dst, src) \
    asm volatile("cp.async.ca.shared.global [%0], [%1], 16;" :: "r"(dst), "l"(src) : "memory")
#define CPA_COMMIT() asm volatile("cp.async.commit_group;" ::: "memory")
#define CPA_WAIT0()  asm volatile("cp.async.wait_group 0;" ::: "memory")

#define LDM4(r0, r1, r2, r3, a) \
    asm volatile("ldmatrix.sync.aligned.m8n8.x4.shared.b16 {%0,%1,%2,%3}, [%4];" \
        : "=r"(r0), "=r"(r1), "=r"(r2), "=r"(r3) : "r"(a))

#define MMA16816(d, a0, a1, a2, a3, b0, b1) \
    asm volatile("mma.sync.aligned.m16n8k16.row.col.f32.f16.f16.f32 " \
        "{%0,%1,%2,%3},{%4,%5,%6,%7},{%8,%9},{%0,%1,%2,%3};" \
        : "+f"((d)[0]), "+f"((d)[1]), "+f"((d)[2]), "+f"((d)[3]) \
        : "r"(a0), "r"(a1), "r"(a2), "r"(a3), "r"(b0), "r"(b1))

// ---------------- prepass: fp32 image -> fp16 scratch ----------------
__global__ void prep_kernel(const float* __restrict__ inp) {
    int g = blockIdx.x * 256 + threadIdx.x;      // 16B units
    int q  = g & 7;
    int n  = (g >> 3) & 255;                     // row = u_local*32 + c
    int ch = (g >> 11) & 7;
    int b  = g >> 14;
    int c  = n & 31;
    int u  = ch * 8 + (n >> 5);
    const float* s = inp + ((size_t)(b * 32 + c) * HWP + u * 64 + q * 8);
    float4 f0 = *(const float4*)s;
    float4 f1 = *(const float4*)(s + 4);
    __half2 h0 = __float22half2_rn(make_float2(f0.x, f0.y));
    __half2 h1 = __float22half2_rn(make_float2(f0.z, f0.w));
    __half2 h2 = __float22half2_rn(make_float2(f1.x, f1.y));
    __half2 h3 = __float22half2_rn(make_float2(f1.z, f1.w));
    uint4 st;
    st.x = *(uint32_t*)&h0; st.y = *(uint32_t*)&h1;
    st.z = *(uint32_t*)&h2; st.w = *(uint32_t*)&h3;
    *(uint4*)(g_fp16 + (((size_t)(b * 8 + ch) * 256 + n) * 64 + q * 8)) = st;
}

// ---------------- main kernel ----------------
__global__ __launch_bounds__(512, 1)
void swapv2_mma(const float* __restrict__ exPx, const float* __restrict__ exPy,
                const float* __restrict__ sigx, const float* __restrict__ sigy,
                float* __restrict__ out)
{
    extern __shared__ char smem[];
    const uint32_t sb = s32(smem);
    const int tid  = threadIdx.x;
    const int lane = tid & 31;
    const int wid  = tid >> 5;
    const int s    = wid >> 1;                  // px strip 0..7 (32 px)
    const int cb   = wid & 1;                   // channel half: 16 ch
    const int tile = blockIdx.x;                // 0..15 (256 px each)
    const int b    = blockIdx.y;

    // ---- stage chunk 0 ----
    {
        const __half* src = g_fp16 + (size_t)(b * 8 + 0) * 16384;
        #pragma unroll
        for (int j = 0; j < 4; j++) {
            int idx = tid + j * 512;
            int q = idx & 7, n = idx >> 3;
            CPA16(sb + SM_B + SW((uint32_t)n * 128 + q * 16), src + n * 64 + q * 8);
        }
        CPA_COMMIT();
    }

    // ---- build wx (A, fp16 swz) / wy (fp16) / row sums ----
    if (tid < 256) {
        int px = tid;
        int pidx = b * HWP + tile * 256 + px;
        float ex = exPx[pidx];
        float iv = 0.5f / (sigx[pidx] * sigx[pidx]);
        float sumx = 0.f;
        #pragma unroll
        for (int j = 0; j < 8; j++) {
            uint32_t hh[4];
            #pragma unroll
            for (int h = 0; h < 4; h++) {
                float d0 = (float)(j * 8 + h * 2) - ex;
                float d1 = d0 + 1.f;
                __half2 h2 = __float22half2_rn(make_float2(__expf(-d0 * d0 * iv),
                                                           __expf(-d1 * d1 * iv)));
                float2 bk = __half22float2(h2);
                sumx += bk.x + bk.y;
                hh[h] = *(uint32_t*)&h2;
            }
            *(uint4*)(smem + SM_A + SW((uint32_t)px * 128 + j * 16)) =
                make_uint4(hh[0], hh[1], hh[2], hh[3]);
        }
        ((float*)(smem + SM_SX))[px] = sumx;
    } else {
        int px = tid - 256;
        int pidx = b * HWP + tile * 256 + px;
        float ey = exPy[pidx];
        float iv = 0.5f / (sigy[pidx] * sigy[pidx]);
        float sumy = 0.f;
        __half* wyp = (__half*)(smem + SM_WY);
        #pragma unroll 8
        for (int u = 0; u < 64; u++) {
            float d = (float)u - ey;
            __half w = __float2half_rn(__expf(-d * d * iv));
            wyp[u * 256 + px] = w;
            sumy += __half2float(w);
        }
        ((float*)(smem + SM_SY))[px] = sumy;
    }
    __syncthreads();

    // ---- resident A fragments: 2 m-tiles x 4 k-steps x 4 regs ----
    uint32_t A[2][4][4];
    {
        int r8 = lane & 7, hi8 = (lane >> 3) & 1, kb = lane >> 4;
        #pragma unroll
        for (int mt = 0; mt < 2; mt++)
            #pragma unroll
            for (int ks = 0; ks < 4; ks++) {
                uint32_t off = (uint32_t)(s * 32 + mt * 16 + r8 + hi8 * 8) * 128
                             + ks * 32 + kb * 16;
                LDM4(A[mt][ks][0], A[mt][ks][1], A[mt][ks][2], A[mt][ks][3],
                     sb + SM_A + SW(off));
            }
    }

    float acc[16];                  // [nb][mt][4]
    #pragma unroll
    for (int i = 0; i < 16; i++) acc[i] = 0.f;

    // ---- chunk loop: wait k, stage k+1, compute k ----
    for (int k = 0; k < 8; k++) {
        CPA_WAIT0();
        __syncthreads();
        if (k < 7) {
            const __half* src = g_fp16 + (size_t)(b * 8 + k + 1) * 16384;
            uint32_t bufo = SM_B + ((k + 1) & 1) * 32768;
            #pragma unroll
            for (int j = 0; j < 4; j++) {
                int idx = tid + j * 512;
                int q = idx & 7, n = idx >> 3;
                CPA16(sb + bufo + SW((uint32_t)n * 128 + q * 16), src + n * 64 + q * 8);
            }
            CPA_COMMIT();
        }

        const uint32_t sbB = sb + SM_B + (k & 1) * 32768;
        const __half* wyp = (const __half*)(smem + SM_WY);
        int g4 = lane >> 2;
        #pragma unroll 1
        for (int uu = 0; uu < 8; uu++) {
            const __half* wyrow = wyp + (k * 8 + uu) * 256;
            #pragma unroll
            for (int nb = 0; nb < 2; nb++) {
                int nrow = uu * 32 + cb * 16 + nb * 8 + (lane & 7);
                uint32_t offb = (uint32_t)nrow * 128 + (lane >> 3) * 16;
                uint32_t bb[8];
                LDM4(bb[0], bb[1], bb[2], bb[3], sbB + SW(offb));
                LDM4(bb[4], bb[5], bb[6], bb[7], sbB + SW(offb + 64));

                float S[8];
                #pragma unroll
                for (int i = 0; i < 8; i++) S[i] = 0.f;
                #pragma unroll
                for (int ks = 0; ks < 4; ks++)
                    #pragma unroll
                    for (int mt = 0; mt < 2; mt++)
                        MMA16816(&S[mt * 4], A[mt][ks][0], A[mt][ks][1],
                                 A[mt][ks][2], A[mt][ks][3], bb[2 * ks], bb[2 * ks + 1]);

                #pragma unroll
                for (int mt = 0; mt < 2; mt++) {
                    int px0 = s * 32 + mt * 16 + g4;
                    float wy0 = __half2float(wyrow[px0]);
                    float wy1 = __half2float(wyrow[px0 + 8]);
                    float* ac = acc + nb * 8 + mt * 4;
                    ac[0] = fmaf(wy0, S[mt * 4 + 0], ac[0]);
                    ac[1] = fmaf(wy0, S[mt * 4 + 1], ac[1]);
                    ac[2] = fmaf(wy1, S[mt * 4 + 2], ac[2]);
                    ac[3] = fmaf(wy1, S[mt * 4 + 3], ac[3]);
                }
            }
        }
    }

    // ---- write out ----
    const float* sxp = (const float*)(smem + SM_SX);
    const float* syp = (const float*)(smem + SM_SY);
    int g4 = lane >> 2, t4 = lane & 3;
    #pragma unroll
    for (int nb = 0; nb < 2; nb++) {
        int c0 = cb * 16 + nb * 8 + t4 * 2;
        size_t base = (size_t)(b * 32 + c0) * HWP + tile * 256;
        #pragma unroll
        for (int mt = 0; mt < 2; mt++) {
            int px0 = s * 32 + mt * 16 + g4;
            int px1 = px0 + 8;
            float iz0 = 1.0f / (sxp[px0] * syp[px0] + 1e-8f);
            float iz1 = 1.0f / (sxp[px1] * syp[px1] + 1e-8f);
            const float* ac = acc + nb * 8 + mt * 4;
            out[base + px0]       = ac[0] * iz0;
            out[base + HWP + px0] = ac[1] * iz0;
            out[base + px1]       = ac[2] * iz1;
            out[base + HWP + px1] = ac[3] * iz1;
        }
    }
}

extern "C" void kernel_launch(void* const* d_in, const int* in_sizes, int n_in,
                              void* d_out, int out_size) {
    (void)in_sizes; (void)n_in; (void)out_size;
    const float* inp  = (const float*)d_in[0];
    const float* exPx = (const float*)d_in[1];
    const float* exPy = (const float*)d_in[2];
    const float* sigx = (const float*)d_in[3];
    const float* sigy = (const float*)d_in[4];
    float* out = (float*)d_out;

    prep_kernel<<<512, 256>>>(inp);
    cudaFuncSetAttribute(swapv2_mma,
                         cudaFuncAttributeMaxDynamicSharedMemorySize, SM_TOT);
    dim3 grid(16, 8);                 // 128 CTAs = one wave
    swapv2_mma<<<grid, 512, SM_TOT>>>(exPx, exPy, sigx, sigy, out);
}